// round 15
// baseline (speedup 1.0000x reference)
#include <cuda_runtime.h>
#include <cuda_fp16.h>
#include <math.h>
#include <stdint.h>

// ---------------------------------------------------------------- constants
#define B_    16
#define T_    1024
#define IN_   1024
#define MEM_  64
#define OUT_  1024
#define C_    32
#define HN_   (2*MEM_ + 2*OUT_)      // 2176
#define NTOK  (B_*T_)                // 16384
#define KMIX  (MEM_*2*C_)            // 4096
#define NCH   8
#define CHLEN (T_/NCH)               // 128

// ---------------------------------------------------------------- scratch
__device__ __half g_h  [(size_t)NTOK * HN_];   // fp16 h (thru/gates path)
__device__ float  g_yg [(size_t)NTOK * 128];   // fp32 side: [0:64)=y-pre, [64:128)=in-gate
__device__ float  g_y  [(size_t)NTOK * MEM_];
__device__ __half g_z16[(size_t)NTOK * OUT_];  // fp16 z (LN is scale-invariant)
__device__ float2 g_sum[(size_t)B_ * NCH * MEM_ * C_];
__device__ __half g_xh [(size_t)NTOK * IN_];
__device__ __half g_w1h[(size_t)HN_  * IN_];
__device__ __half g_w2h[(size_t)OUT_ * KMIX];
__device__ __half g_srh[(size_t)NTOK * KMIX];

// ---------------------------------------------------------------- utils
__device__ __forceinline__ uint32_t smem_u32_of(const void* p) {
    uint32_t a;
    asm("{ .reg .u64 t; cvta.to.shared.u64 t, %1; cvt.u32.u64 %0, t; }"
        : "=r"(a) : "l"(p));
    return a;
}

#define LDSM4(r0, r1, r2, r3, addr)                                         \
    asm volatile("ldmatrix.sync.aligned.m8n8.x4.shared.b16 {%0,%1,%2,%3}, [%4];" \
        : "=r"(r0), "=r"(r1), "=r"(r2), "=r"(r3) : "r"(addr))

#define MMA_F16(c, a, b)                                                    \
    asm volatile("mma.sync.aligned.m16n8k16.row.col.f32.f16.f16.f32 "       \
        "{%0,%1,%2,%3}, {%4,%5,%6,%7}, {%8,%9}, {%0,%1,%2,%3};"             \
        : "+f"((c)[0]), "+f"((c)[1]), "+f"((c)[2]), "+f"((c)[3])            \
        : "r"((a)[0]), "r"((a)[1]), "r"((a)[2]), "r"((a)[3]),               \
          "r"((b)[0]), "r"((b)[1]))

#define CP_ASYNC16(sp, gp)                                                  \
    asm volatile("cp.async.cg.shared.global [%0], [%1], 16;"                \
        :: "r"(sp), "l"(gp))
#define CP_COMMIT()   asm volatile("cp.async.commit_group;" ::: "memory")
#define CP_WAIT_1()   asm volatile("cp.async.wait_group 1;" ::: "memory")
#define CP_WAIT_0()   asm volatile("cp.async.wait_group 0;" ::: "memory")

// ---------------------------------------------------------------- split
__global__ void splitw_kernel(const float* __restrict__ src,
                              __half* __restrict__ hi, int n4)
{
    int i = blockIdx.x * blockDim.x + threadIdx.x;
    if (i >= n4) return;
    float4 v = ((const float4*)src)[i];
    ((__half2*)hi)[i*2+0] = __halves2half2(__float2half_rn(v.x), __float2half_rn(v.y));
    ((__half2*)hi)[i*2+1] = __halves2half2(__float2half_rn(v.z), __float2half_rn(v.w));
}

// ---------------------------------------------------------------- MMA GEMM
// C[M,N] = Ah @ Bh^T + bias  (fp32 accum, fp16 mma.sync)
// CTA 128x128, 256 thr / 8 warps (warp tile 64x32), K-chunk 64,
// 3-stage cp.async, 2 CTAs/SM.
// MODE 1: fp16 C + fp32 side buffer for cols [0,64)+[1088,1152)  (GEMM1)
// MODE 2: fp16 C plain                                            (GEMM2)
#define PADW    72
#define TB      (128 * PADW * 2)           // bytes per tile: 18432
#define STG_B   (2 * TB)                   // bytes per stage: 36864
#define NST     3
#define SMEM_MMA (NST * STG_B)             // 110592

__device__ __forceinline__ void ld_tile_async(uint32_t sdst,
                                              const __half* __restrict__ g,
                                              int row0, int K, int k0, int tid)
{
#pragma unroll
    for (int it = 0; it < 4; ++it) {
        int idx = tid + (it << 8);          // 0..1023 16B vectors
        int row = idx >> 3, c8 = idx & 7;
        const void* gp = g + (size_t)(row0 + row) * K + k0 + c8 * 8;
        uint32_t sp = sdst + row * 144 + c8 * 16;
        CP_ASYNC16(sp, gp);
    }
}

__device__ __forceinline__ void ld_chunk(uint32_t sbase,
                                         const __half* Ah, const __half* Bh,
                                         int bm, int bn, int K, int k0, int tid)
{
    ld_tile_async(sbase,      Ah, bm, K, k0, tid);
    ld_tile_async(sbase + TB, Bh, bn, K, k0, tid);
    CP_COMMIT();
}

template<int MODE>
__global__ __launch_bounds__(256, 2)
void gemm_mma(const __half* __restrict__ Ah, const __half* __restrict__ Bh,
              const float* __restrict__ bias, __half* __restrict__ Cout,
              int K, int N)
{
    extern __shared__ char smem[];
    const uint32_t smb = smem_u32_of(smem);
    const int tid  = threadIdx.x;
    const int wid  = tid >> 5;
    const int lane = tid & 31;
    const int bm   = blockIdx.y << 7;
    const int bn   = blockIdx.x << 7;
    const int m0   = (wid & 1) * 64;
    const int n0   = (wid >> 1) * 32;

    float acc[4][4][4];
#pragma unroll
    for (int i = 0; i < 4; ++i)
#pragma unroll
        for (int j = 0; j < 4; ++j)
#pragma unroll
            for (int k = 0; k < 4; ++k) acc[i][j][k] = 0.f;

    const int nk = K >> 6;

    ld_chunk(smb,         Ah, Bh, bm, bn, K, 0,  tid);
    ld_chunk(smb + STG_B, Ah, Bh, bm, bn, K, 64, tid);

    const int arow  = (lane & 7) + ((lane >> 3) & 1) * 8;
    const int akoff = (lane >> 4) * 8;
    const int bgrp  = lane >> 3;
    const int brow  = (lane & 7) + (bgrp >> 1) * 8;
    const int bkoff = (bgrp & 1) * 8;

    int stage = 0;
    for (int i = 0; i < nk; ++i) {
        if (i + 1 < nk) CP_WAIT_1(); else CP_WAIT_0();
        __syncthreads();

        if (i + 2 < nk) {
            int st = stage + 2; if (st >= NST) st -= NST;
            ld_chunk(smb + st * STG_B, Ah, Bh, bm, bn, K, (i + 2) << 6, tid);
        }

        const uint32_t sAh = smb + stage * STG_B;
        const uint32_t sBh = sAh + TB;

#pragma unroll
        for (int kk = 0; kk < 4; ++kk) {
            uint32_t ah[4][4], bh[4][2];
#pragma unroll
            for (int mt = 0; mt < 4; ++mt) {
                uint32_t aoff = (uint32_t)(m0 + mt * 16 + arow) * 144
                              + (uint32_t)(kk * 16 + akoff) * 2;
                LDSM4(ah[mt][0], ah[mt][1], ah[mt][2], ah[mt][3], sAh + aoff);
            }
#pragma unroll
            for (int hf = 0; hf < 2; ++hf) {
                uint32_t boff = (uint32_t)(n0 + hf * 16 + brow) * 144
                              + (uint32_t)(kk * 16 + bkoff) * 2;
                uint32_t t0, t1, t2, t3;
                LDSM4(t0, t1, t2, t3, sBh + boff);
                bh[hf*2][0] = t0; bh[hf*2][1] = t1;
                bh[hf*2+1][0] = t2; bh[hf*2+1][1] = t3;
            }
#pragma unroll
            for (int mt = 0; mt < 4; ++mt)
#pragma unroll
                for (int nt = 0; nt < 4; ++nt)
                    MMA_F16(acc[mt][nt], ah[mt], bh[nt]);
        }
        if (++stage >= NST) stage = 0;
    }

    // epilogue (+bias), fp16 store
#pragma unroll
    for (int mt = 0; mt < 4; ++mt) {
#pragma unroll
        for (int nt = 0; nt < 4; ++nt) {
            int row = bm + m0 + mt * 16 + (lane >> 2);
            int col = bn + n0 + nt * 8 + 2 * (lane & 3);
            float b0 = bias[col], b1 = bias[col + 1];
            float c00 = acc[mt][nt][0] + b0, c01 = acc[mt][nt][1] + b1;
            float c10 = acc[mt][nt][2] + b0, c11 = acc[mt][nt][3] + b1;
            *(__half2*)(Cout + (size_t)row * N + col) =
                __halves2half2(__float2half_rn(c00), __float2half_rn(c01));
            *(__half2*)(Cout + (size_t)(row + 8) * N + col) =
                __halves2half2(__float2half_rn(c10), __float2half_rn(c11));
            if (MODE == 1) {
                int sc = -1;
                if (col < MEM_)                          sc = col;          // y-pre
                else if (col >= MEM_ + OUT_ && col < MEM_ + OUT_ + MEM_)
                                                         sc = 64 + col - (MEM_ + OUT_);
                if (sc >= 0) {
                    *(float2*)(g_yg + (size_t)row * 128 + sc)       = make_float2(c00, c01);
                    *(float2*)(g_yg + (size_t)(row + 8) * 128 + sc) = make_float2(c10, c11);
                }
            }
        }
    }
}

// ---------------------------------------------------------------- gating
__global__ void gating_kernel()
{
    int i = blockIdx.x * blockDim.x + threadIdx.x;   // over NTOK*MEM_/4
    int t = i >> 4;
    int m4 = (i & 15) << 2;
    const float* gr = g_yg + (size_t)t * 128;
    float4 hy = *(const float4*)(gr + m4);
    float4 hg = *(const float4*)(gr + 64 + m4);
    float4 yv;
    yv.x = hy.x * (1.f / (1.f + __expf(-hg.x)));
    yv.y = hy.y * (1.f / (1.f + __expf(-hg.y)));
    yv.z = hy.z * (1.f / (1.f + __expf(-hg.z)));
    yv.w = hy.w * (1.f / (1.f + __expf(-hg.w)));
    *(float4*)(g_y + (size_t)t * MEM_ + m4) = yv;
}

// ---------------------------------------------------------------- scan
__device__ __forceinline__ void scan_gamma(const float* a, const float* bfreq,
                                           int m, int c, float& gr, float& gi)
{
    float r   = expf(-fabsf(a[m]));
    float ang = bfreq[c];
    gr = r * cosf(ang);
    gi = r * sinf(ang);
}

__global__ void scan_phase1(const float* __restrict__ a,
                            const float* __restrict__ bfreq)
{
    int g = blockIdx.x * blockDim.x + threadIdx.x;   // B*NCH*MEM*C
    int c  = g & (C_ - 1);
    int m  = (g >> 5) & (MEM_ - 1);
    int ch = (g >> 11) & (NCH - 1);
    int b  = g >> 14;

    float gr, gi;
    scan_gamma(a, bfreq, m, c, gr, gi);

    const float* yb = g_y + ((size_t)b * T_ + ch * CHLEN) * MEM_ + m;
    float sr = 0.f, si = 0.f;
    for (int t = 0; t < CHLEN; ++t) {
        float yv = yb[(size_t)t * MEM_];
        float nr = fmaf(gr, sr, fmaf(-gi, si, yv));
        float ni = fmaf(gr, si, gi * sr);
        sr = nr; si = ni;
    }
    g_sum[g] = make_float2(sr, si);
}

__global__ void scan_phase2(const float* __restrict__ a,
                            const float* __restrict__ bfreq,
                            float2* __restrict__ st,
                            float*  __restrict__ st_real)
{
    int g = blockIdx.x * blockDim.x + threadIdx.x;
    int c  = g & (C_ - 1);
    int m  = (g >> 5) & (MEM_ - 1);
    int ch = (g >> 11) & (NCH - 1);
    int b  = g >> 14;

    float gr, gi;
    scan_gamma(a, bfreq, m, c, gr, gi);

    float pr = gr, pi = gi;
#pragma unroll
    for (int s = 0; s < 7; ++s) {
        float nr = pr * pr - pi * pi;
        float ni = 2.f * pr * pi;
        pr = nr; pi = ni;
    }

    float cr = 0.f, ci = 0.f;
    const size_t sum_stride = (size_t)MEM_ * C_;
    const size_t sum_base = ((size_t)b * NCH) * sum_stride + (size_t)m * C_ + c;
    for (int j = 0; j < ch; ++j) {
        float tr = cr * pr - ci * pi;
        float ti = cr * pi + ci * pr;
        float2 S = g_sum[sum_base + (size_t)j * sum_stride];
        cr = tr + S.x;
        ci = ti + S.y;
    }

    const int t0 = ch * CHLEN;
    const float* yb = g_y + ((size_t)b * T_ + t0) * MEM_ + m;
    const size_t base = (((size_t)b * T_ + t0) * MEM_ + m) * C_ + c;
    float2* sb = st ? st + base : 0;
    float*  rb = st_real ? st_real + base : 0;
    __half2* sh = (__half2*)g_srh + base;

    float sr = cr, si = ci;
    for (int t = 0; t < CHLEN; ++t) {
        float yv = yb[(size_t)t * MEM_];
        float nr = fmaf(gr, sr, fmaf(-gi, si, yv));
        float ni = fmaf(gr, si, gi * sr);
        sr = nr; si = ni;
        const size_t o = (size_t)t * (MEM_ * C_);
        if (sb) sb[o] = make_float2(sr, si);
        if (rb) rb[o] = sr;
        sh[o] = __halves2half2(__float2half_rn(sr), __float2half_rn(si));
    }
}

// ---------------------------------------------------------------- LN epi
__global__ __launch_bounds__(256)
void ln_epilogue(float* __restrict__ out)
{
    __shared__ float wsum[8], wsq[8];
    const int row = blockIdx.x;
    const int tid = threadIdx.x;
    const int lane = tid & 31, wid = tid >> 5;
    const __half* zr = g_z16 + (size_t)row * OUT_;

    float v[4];
    float s = 0.f, sq = 0.f;
#pragma unroll
    for (int j = 0; j < 4; ++j) {
        v[j] = __half2float(zr[tid + (j << 8)]);
        s += v[j];
        sq = fmaf(v[j], v[j], sq);
    }
#pragma unroll
    for (int off = 16; off > 0; off >>= 1) {
        s  += __shfl_xor_sync(0xffffffff, s,  off);
        sq += __shfl_xor_sync(0xffffffff, sq, off);
    }
    if (lane == 0) { wsum[wid] = s; wsq[wid] = sq; }
    __syncthreads();
    float ts = 0.f, tq = 0.f;
#pragma unroll
    for (int w = 0; w < 8; ++w) { ts += wsum[w]; tq += wsq[w]; }
    float mu  = ts * (1.f / OUT_);
    float var = tq * (1.f / OUT_) - mu * mu;
    float inv = rsqrtf(var + 1e-5f);

    const __half* hr = g_h + (size_t)row * HN_;
#pragma unroll
    for (int j = 0; j < 4; ++j) {
        int o = tid + (j << 8);
        float hg   = __half2float(hr[MEM_ + OUT_ + MEM_ + o]);
        float og   = 1.f / (1.f + expf(-hg));
        float thru = __half2float(hr[MEM_ + o]);
        out[(size_t)row * OUT_ + o] = (v[j] - mu) * inv * og + thru * (1.f - og);
    }
}

// ---------------------------------------------------------------- launch
extern "C" void kernel_launch(void* const* d_in, const int* in_sizes, int n_in,
                              void* d_out, int out_size)
{
    (void)in_sizes; (void)n_in;
    const float* x     = (const float*)d_in[0];
    const float* pre_w = (const float*)d_in[1];
    const float* pre_b = (const float*)d_in[2];
    const float* a     = (const float*)d_in[3];
    const float* bfr   = (const float*)d_in[4];
    const float* mix_w = (const float*)d_in[5];
    const float* mix_b = (const float*)d_in[6];
    float* out = (float*)d_out;

    cudaFuncSetAttribute(gemm_mma<1>, cudaFuncAttributeMaxDynamicSharedMemorySize,
                         SMEM_MMA);
    cudaFuncSetAttribute(gemm_mma<2>, cudaFuncAttributeMaxDynamicSharedMemorySize,
                         SMEM_MMA);

    __half *hbuf, *zbuf, *xh, *w1h, *w2h, *srh;
    cudaGetSymbolAddress((void**)&hbuf, g_h);
    cudaGetSymbolAddress((void**)&zbuf, g_z16);
    cudaGetSymbolAddress((void**)&xh,  g_xh);
    cudaGetSymbolAddress((void**)&w1h, g_w1h);
    cudaGetSymbolAddress((void**)&w2h, g_w2h);
    cudaGetSymbolAddress((void**)&srh, g_srh);

    const long long OUT_ELEMS = (long long)NTOK * OUT_;        // 16,777,216
    const long long ST_CPLX_F = 2LL * NTOK * MEM_ * C_;        // 67,108,864
    const long long ST_REAL_F = (long long)NTOK * MEM_ * C_;   // 33,554,432
    const long long avail = (long long)out_size - OUT_ELEMS;

    float2* st_i = 0;
    float*  st_r = 0;
    if (avail >= ST_CPLX_F)       st_i = (float2*)(out + OUT_ELEMS);
    else if (avail >= ST_REAL_F)  st_r = out + OUT_ELEMS;

    // fp32 -> fp16 rounds
    splitw_kernel<<<(NTOK*IN_/4 + 255)/256, 256>>>(x, xh, NTOK*IN_/4);
    splitw_kernel<<<(HN_*IN_/4 + 255)/256, 256>>>(pre_w, w1h, HN_*IN_/4);
    splitw_kernel<<<(OUT_*KMIX/4 + 255)/256, 256>>>(mix_w, w2h, OUT_*KMIX/4);

    // 1) h = x @ pre_w^T + pre_b  -> fp16 h + fp32 side cols
    gemm_mma<1><<<dim3(HN_/128, NTOK/128), 256, SMEM_MMA>>>(
        xh, w1h, pre_b, hbuf, IN_, HN_);
    // 2) gated scan input (fp32 path via g_yg)
    gating_kernel<<<(NTOK * MEM_ / 4) / 256, 256>>>();
    // 3) two-phase parallel scan -> states output + fp16 sr
    const int nscan = B_ * NCH * MEM_ * C_;      // 262144
    scan_phase1<<<nscan / 256, 256>>>(a, bfr);
    scan_phase2<<<nscan / 256, 256>>>(a, bfr, st_i, st_r);
    // 4) z = sr @ mix_w^T + mix_b  -> fp16 z
    gemm_mma<2><<<dim3(OUT_/128, NTOK/128), 256, SMEM_MMA>>>(
        srh, w2h, mix_b, zbuf, KMIX, OUT_);
    // 5) LN + gated mix
    ln_epilogue<<<NTOK, 256>>>(out);
}

// round 16
// speedup vs baseline: 1.0056x; 1.0056x over previous
#include <cuda_runtime.h>
#include <cuda_fp16.h>
#include <math.h>
#include <stdint.h>

// ---------------------------------------------------------------- constants
#define B_    16
#define T_    1024
#define IN_   1024
#define MEM_  64
#define OUT_  1024
#define C_    32
#define HN_   (2*MEM_ + 2*OUT_)      // 2176
#define NTOK  (B_*T_)                // 16384
#define KMIX  (MEM_*2*C_)            // 4096
#define NCH   8
#define CHLEN (T_/NCH)               // 128

// split sizes (in float4 units)
#define N4_X   (NTOK*IN_/4)          // 4,194,304
#define N4_W1  (HN_*IN_/4)           //   557,056
#define N4_W2  (OUT_*KMIX/4)         // 1,048,576
#define N4_ALL (N4_X + N4_W1 + N4_W2)

// ---------------------------------------------------------------- scratch
__device__ __half g_h  [(size_t)NTOK * HN_];   // fp16 h (thru/gates path)
__device__ float  g_yg [(size_t)NTOK * 128];   // fp32 side: [0:64)=y-pre, [64:128)=in-gate
__device__ float  g_y  [(size_t)NTOK * MEM_];
__device__ float  g_z  [(size_t)NTOK * OUT_];  // fp32 z
__device__ float2 g_sum[(size_t)B_ * NCH * MEM_ * C_];
__device__ __half g_xh [(size_t)NTOK * IN_];
__device__ __half g_w1h[(size_t)HN_  * IN_];
__device__ __half g_w2h[(size_t)OUT_ * KMIX];
__device__ __half g_srh[(size_t)NTOK * KMIX];

// ---------------------------------------------------------------- utils
__device__ __forceinline__ uint32_t smem_u32_of(const void* p) {
    uint32_t a;
    asm("{ .reg .u64 t; cvta.to.shared.u64 t, %1; cvt.u32.u64 %0, t; }"
        : "=r"(a) : "l"(p));
    return a;
}

#define LDSM4(r0, r1, r2, r3, addr)                                         \
    asm volatile("ldmatrix.sync.aligned.m8n8.x4.shared.b16 {%0,%1,%2,%3}, [%4];" \
        : "=r"(r0), "=r"(r1), "=r"(r2), "=r"(r3) : "r"(addr))

#define MMA_F16(c, a, b)                                                    \
    asm volatile("mma.sync.aligned.m16n8k16.row.col.f32.f16.f16.f32 "       \
        "{%0,%1,%2,%3}, {%4,%5,%6,%7}, {%8,%9}, {%0,%1,%2,%3};"             \
        : "+f"((c)[0]), "+f"((c)[1]), "+f"((c)[2]), "+f"((c)[3])            \
        : "r"((a)[0]), "r"((a)[1]), "r"((a)[2]), "r"((a)[3]),               \
          "r"((b)[0]), "r"((b)[1]))

#define CP_ASYNC16(sp, gp)                                                  \
    asm volatile("cp.async.cg.shared.global [%0], [%1], 16;"                \
        :: "r"(sp), "l"(gp))
#define CP_COMMIT()   asm volatile("cp.async.commit_group;" ::: "memory")
#define CP_WAIT_1()   asm volatile("cp.async.wait_group 1;" ::: "memory")
#define CP_WAIT_0()   asm volatile("cp.async.wait_group 0;" ::: "memory")

// ---------------------------------------------------------------- split
// One launch converts x, pre_w, mix_w fp32 -> fp16 via a flattened index.
__device__ __forceinline__ void cvt4(const float* __restrict__ src,
                                     __half* __restrict__ dst, int i)
{
    float4 v = ((const float4*)src)[i];
    ((__half2*)dst)[i*2+0] = __halves2half2(__float2half_rn(v.x), __float2half_rn(v.y));
    ((__half2*)dst)[i*2+1] = __halves2half2(__float2half_rn(v.z), __float2half_rn(v.w));
}

__global__ void split_all_kernel(const float* __restrict__ x,
                                 const float* __restrict__ w1,
                                 const float* __restrict__ w2)
{
    int i = blockIdx.x * blockDim.x + threadIdx.x;
    if (i < N4_X)                    cvt4(x,  g_xh,  i);
    else if (i < N4_X + N4_W1)       cvt4(w1, g_w1h, i - N4_X);
    else if (i < N4_ALL)             cvt4(w2, g_w2h, i - N4_X - N4_W1);
}

// ---------------------------------------------------------------- MMA GEMM
// C[M,N] = Ah @ Bh^T + bias  (fp32 accum, fp16 mma.sync)
// CTA 128x128, 256 thr / 8 warps (warp tile 64x32), K-chunk 64,
// 3-stage cp.async, 2 CTAs/SM.
// MODE 0: fp32 C (GEMM2 -> z)
// MODE 1: fp16 C + fp32 side buffer for cols [0,64)+[1088,1152) (GEMM1)
#define PADW    72
#define TB      (128 * PADW * 2)           // bytes per tile: 18432
#define STG_B   (2 * TB)                   // bytes per stage: 36864
#define NST     3
#define SMEM_MMA (NST * STG_B)             // 110592

__device__ __forceinline__ void ld_tile_async(uint32_t sdst,
                                              const __half* __restrict__ g,
                                              int row0, int K, int k0, int tid)
{
#pragma unroll
    for (int it = 0; it < 4; ++it) {
        int idx = tid + (it << 8);          // 0..1023 16B vectors
        int row = idx >> 3, c8 = idx & 7;
        const void* gp = g + (size_t)(row0 + row) * K + k0 + c8 * 8;
        uint32_t sp = sdst + row * 144 + c8 * 16;
        CP_ASYNC16(sp, gp);
    }
}

__device__ __forceinline__ void ld_chunk(uint32_t sbase,
                                         const __half* Ah, const __half* Bh,
                                         int bm, int bn, int K, int k0, int tid)
{
    ld_tile_async(sbase,      Ah, bm, K, k0, tid);
    ld_tile_async(sbase + TB, Bh, bn, K, k0, tid);
    CP_COMMIT();
}

template<int MODE>
__global__ __launch_bounds__(256, 2)
void gemm_mma(const __half* __restrict__ Ah, const __half* __restrict__ Bh,
              const float* __restrict__ bias, void* __restrict__ CoutV,
              int K, int N)
{
    extern __shared__ char smem[];
    const uint32_t smb = smem_u32_of(smem);
    const int tid  = threadIdx.x;
    const int wid  = tid >> 5;
    const int lane = tid & 31;
    const int bm   = blockIdx.y << 7;
    const int bn   = blockIdx.x << 7;
    const int m0   = (wid & 1) * 64;
    const int n0   = (wid >> 1) * 32;

    float acc[4][4][4];
#pragma unroll
    for (int i = 0; i < 4; ++i)
#pragma unroll
        for (int j = 0; j < 4; ++j)
#pragma unroll
            for (int k = 0; k < 4; ++k) acc[i][j][k] = 0.f;

    const int nk = K >> 6;

    ld_chunk(smb,         Ah, Bh, bm, bn, K, 0,  tid);
    ld_chunk(smb + STG_B, Ah, Bh, bm, bn, K, 64, tid);

    const int arow  = (lane & 7) + ((lane >> 3) & 1) * 8;
    const int akoff = (lane >> 4) * 8;
    const int bgrp  = lane >> 3;
    const int brow  = (lane & 7) + (bgrp >> 1) * 8;
    const int bkoff = (bgrp & 1) * 8;

    int stage = 0;
    for (int i = 0; i < nk; ++i) {
        if (i + 1 < nk) CP_WAIT_1(); else CP_WAIT_0();
        __syncthreads();

        if (i + 2 < nk) {
            int st = stage + 2; if (st >= NST) st -= NST;
            ld_chunk(smb + st * STG_B, Ah, Bh, bm, bn, K, (i + 2) << 6, tid);
        }

        const uint32_t sAh = smb + stage * STG_B;
        const uint32_t sBh = sAh + TB;

#pragma unroll
        for (int kk = 0; kk < 4; ++kk) {
            uint32_t ah[4][4], bh[4][2];
#pragma unroll
            for (int mt = 0; mt < 4; ++mt) {
                uint32_t aoff = (uint32_t)(m0 + mt * 16 + arow) * 144
                              + (uint32_t)(kk * 16 + akoff) * 2;
                LDSM4(ah[mt][0], ah[mt][1], ah[mt][2], ah[mt][3], sAh + aoff);
            }
#pragma unroll
            for (int hf = 0; hf < 2; ++hf) {
                uint32_t boff = (uint32_t)(n0 + hf * 16 + brow) * 144
                              + (uint32_t)(kk * 16 + bkoff) * 2;
                uint32_t t0, t1, t2, t3;
                LDSM4(t0, t1, t2, t3, sBh + boff);
                bh[hf*2][0] = t0; bh[hf*2][1] = t1;
                bh[hf*2+1][0] = t2; bh[hf*2+1][1] = t3;
            }
#pragma unroll
            for (int mt = 0; mt < 4; ++mt)
#pragma unroll
                for (int nt = 0; nt < 4; ++nt)
                    MMA_F16(acc[mt][nt], ah[mt], bh[nt]);
        }
        if (++stage >= NST) stage = 0;
    }

    // epilogue (+bias)
#pragma unroll
    for (int mt = 0; mt < 4; ++mt) {
#pragma unroll
        for (int nt = 0; nt < 4; ++nt) {
            int row = bm + m0 + mt * 16 + (lane >> 2);
            int col = bn + n0 + nt * 8 + 2 * (lane & 3);
            float b0 = bias[col], b1 = bias[col + 1];
            float c00 = acc[mt][nt][0] + b0, c01 = acc[mt][nt][1] + b1;
            float c10 = acc[mt][nt][2] + b0, c11 = acc[mt][nt][3] + b1;
            if (MODE == 0) {
                float* Cout = (float*)CoutV;
                *(float2*)(Cout + (size_t)row * N + col)       = make_float2(c00, c01);
                *(float2*)(Cout + (size_t)(row + 8) * N + col) = make_float2(c10, c11);
            } else {
                __half* Cout = (__half*)CoutV;
                *(__half2*)(Cout + (size_t)row * N + col) =
                    __halves2half2(__float2half_rn(c00), __float2half_rn(c01));
                *(__half2*)(Cout + (size_t)(row + 8) * N + col) =
                    __halves2half2(__float2half_rn(c10), __float2half_rn(c11));
                int sc = -1;
                if (col < MEM_)                          sc = col;          // y-pre
                else if (col >= MEM_ + OUT_ && col < MEM_ + OUT_ + MEM_)
                                                         sc = 64 + col - (MEM_ + OUT_);
                if (sc >= 0) {
                    *(float2*)(g_yg + (size_t)row * 128 + sc)       = make_float2(c00, c01);
                    *(float2*)(g_yg + (size_t)(row + 8) * 128 + sc) = make_float2(c10, c11);
                }
            }
        }
    }
}

// ---------------------------------------------------------------- gating
__global__ void gating_kernel()
{
    int i = blockIdx.x * blockDim.x + threadIdx.x;   // over NTOK*MEM_/4
    int t = i >> 4;
    int m4 = (i & 15) << 2;
    const float* gr = g_yg + (size_t)t * 128;
    float4 hy = *(const float4*)(gr + m4);
    float4 hg = *(const float4*)(gr + 64 + m4);
    float4 yv;
    yv.x = hy.x * (1.f / (1.f + __expf(-hg.x)));
    yv.y = hy.y * (1.f / (1.f + __expf(-hg.y)));
    yv.z = hy.z * (1.f / (1.f + __expf(-hg.z)));
    yv.w = hy.w * (1.f / (1.f + __expf(-hg.w)));
    *(float4*)(g_y + (size_t)t * MEM_ + m4) = yv;
}

// ---------------------------------------------------------------- scan
__device__ __forceinline__ void scan_gamma(const float* a, const float* bfreq,
                                           int m, int c, float& gr, float& gi)
{
    float r   = expf(-fabsf(a[m]));
    float ang = bfreq[c];
    gr = r * cosf(ang);
    gi = r * sinf(ang);
}

__global__ void scan_phase1(const float* __restrict__ a,
                            const float* __restrict__ bfreq)
{
    int g = blockIdx.x * blockDim.x + threadIdx.x;   // B*NCH*MEM*C
    int c  = g & (C_ - 1);
    int m  = (g >> 5) & (MEM_ - 1);
    int ch = (g >> 11) & (NCH - 1);
    int b  = g >> 14;

    float gr, gi;
    scan_gamma(a, bfreq, m, c, gr, gi);

    const float* yb = g_y + ((size_t)b * T_ + ch * CHLEN) * MEM_ + m;
    float sr = 0.f, si = 0.f;
    for (int t = 0; t < CHLEN; ++t) {
        float yv = yb[(size_t)t * MEM_];
        float nr = fmaf(gr, sr, fmaf(-gi, si, yv));
        float ni = fmaf(gr, si, gi * sr);
        sr = nr; si = ni;
    }
    g_sum[g] = make_float2(sr, si);
}

__global__ void scan_phase2(const float* __restrict__ a,
                            const float* __restrict__ bfreq,
                            float2* __restrict__ st,
                            float*  __restrict__ st_real)
{
    int g = blockIdx.x * blockDim.x + threadIdx.x;
    int c  = g & (C_ - 1);
    int m  = (g >> 5) & (MEM_ - 1);
    int ch = (g >> 11) & (NCH - 1);
    int b  = g >> 14;

    float gr, gi;
    scan_gamma(a, bfreq, m, c, gr, gi);

    float pr = gr, pi = gi;
#pragma unroll
    for (int s = 0; s < 7; ++s) {
        float nr = pr * pr - pi * pi;
        float ni = 2.f * pr * pi;
        pr = nr; pi = ni;
    }

    float cr = 0.f, ci = 0.f;
    const size_t sum_stride = (size_t)MEM_ * C_;
    const size_t sum_base = ((size_t)b * NCH) * sum_stride + (size_t)m * C_ + c;
    for (int j = 0; j < ch; ++j) {
        float tr = cr * pr - ci * pi;
        float ti = cr * pi + ci * pr;
        float2 S = g_sum[sum_base + (size_t)j * sum_stride];
        cr = tr + S.x;
        ci = ti + S.y;
    }

    const int t0 = ch * CHLEN;
    const float* yb = g_y + ((size_t)b * T_ + t0) * MEM_ + m;
    const size_t base = (((size_t)b * T_ + t0) * MEM_ + m) * C_ + c;
    float2* sb = st ? st + base : 0;
    float*  rb = st_real ? st_real + base : 0;
    __half2* sh = (__half2*)g_srh + base;

    float sr = cr, si = ci;
    for (int t = 0; t < CHLEN; ++t) {
        float yv = yb[(size_t)t * MEM_];
        float nr = fmaf(gr, sr, fmaf(-gi, si, yv));
        float ni = fmaf(gr, si, gi * sr);
        sr = nr; si = ni;
        const size_t o = (size_t)t * (MEM_ * C_);
        if (sb) sb[o] = make_float2(sr, si);
        if (rb) rb[o] = sr;
        sh[o] = __halves2half2(__float2half_rn(sr), __float2half_rn(si));
    }
}

// ---------------------------------------------------------------- LN epi
__global__ __launch_bounds__(256)
void ln_epilogue(float* __restrict__ out)
{
    __shared__ float wsum[8], wsq[8];
    const int row = blockIdx.x;
    const int tid = threadIdx.x;
    const int lane = tid & 31, wid = tid >> 5;
    const float* zr = g_z + (size_t)row * OUT_;

    float v[4];
    float s = 0.f, sq = 0.f;
#pragma unroll
    for (int j = 0; j < 4; ++j) {
        v[j] = zr[tid + (j << 8)];
        s += v[j];
        sq = fmaf(v[j], v[j], sq);
    }
#pragma unroll
    for (int off = 16; off > 0; off >>= 1) {
        s  += __shfl_xor_sync(0xffffffff, s,  off);
        sq += __shfl_xor_sync(0xffffffff, sq, off);
    }
    if (lane == 0) { wsum[wid] = s; wsq[wid] = sq; }
    __syncthreads();
    float ts = 0.f, tq = 0.f;
#pragma unroll
    for (int w = 0; w < 8; ++w) { ts += wsum[w]; tq += wsq[w]; }
    float mu  = ts * (1.f / OUT_);
    float var = tq * (1.f / OUT_) - mu * mu;
    float inv = rsqrtf(var + 1e-5f);

    const __half* hr = g_h + (size_t)row * HN_;
#pragma unroll
    for (int j = 0; j < 4; ++j) {
        int o = tid + (j << 8);
        float hg   = __half2float(hr[MEM_ + OUT_ + MEM_ + o]);
        float og   = 1.f / (1.f + expf(-hg));
        float thru = __half2float(hr[MEM_ + o]);
        out[(size_t)row * OUT_ + o] = (v[j] - mu) * inv * og + thru * (1.f - og);
    }
}

// ---------------------------------------------------------------- launch
extern "C" void kernel_launch(void* const* d_in, const int* in_sizes, int n_in,
                              void* d_out, int out_size)
{
    (void)in_sizes; (void)n_in;
    const float* x     = (const float*)d_in[0];
    const float* pre_w = (const float*)d_in[1];
    const float* pre_b = (const float*)d_in[2];
    const float* a     = (const float*)d_in[3];
    const float* bfr   = (const float*)d_in[4];
    const float* mix_w = (const float*)d_in[5];
    const float* mix_b = (const float*)d_in[6];
    float* out = (float*)d_out;

    cudaFuncSetAttribute(gemm_mma<0>, cudaFuncAttributeMaxDynamicSharedMemorySize,
                         SMEM_MMA);
    cudaFuncSetAttribute(gemm_mma<1>, cudaFuncAttributeMaxDynamicSharedMemorySize,
                         SMEM_MMA);

    float *zbuf;
    __half *hbuf, *xh, *w1h, *w2h, *srh;
    cudaGetSymbolAddress((void**)&hbuf, g_h);
    cudaGetSymbolAddress((void**)&zbuf, g_z);
    cudaGetSymbolAddress((void**)&xh,  g_xh);
    cudaGetSymbolAddress((void**)&w1h, g_w1h);
    cudaGetSymbolAddress((void**)&w2h, g_w2h);
    cudaGetSymbolAddress((void**)&srh, g_srh);

    const long long OUT_ELEMS = (long long)NTOK * OUT_;        // 16,777,216
    const long long ST_CPLX_F = 2LL * NTOK * MEM_ * C_;        // 67,108,864
    const long long ST_REAL_F = (long long)NTOK * MEM_ * C_;   // 33,554,432
    const long long avail = (long long)out_size - OUT_ELEMS;

    float2* st_i = 0;
    float*  st_r = 0;
    if (avail >= ST_CPLX_F)       st_i = (float2*)(out + OUT_ELEMS);
    else if (avail >= ST_REAL_F)  st_r = out + OUT_ELEMS;

    // fp32 -> fp16 rounds (single fused launch for x, pre_w, mix_w)
    split_all_kernel<<<(N4_ALL + 255)/256, 256>>>(x, pre_w, mix_w);

    // 1) h = x @ pre_w^T + pre_b  -> fp16 h + fp32 side cols
    gemm_mma<1><<<dim3(HN_/128, NTOK/128), 256, SMEM_MMA>>>(
        xh, w1h, pre_b, hbuf, IN_, HN_);
    // 2) gated scan input (fp32 path via g_yg)
    gating_kernel<<<(NTOK * MEM_ / 4) / 256, 256>>>();
    // 3) two-phase parallel scan -> states output + fp16 sr
    const int nscan = B_ * NCH * MEM_ * C_;      // 262144
    scan_phase1<<<nscan / 256, 256>>>(a, bfr);
    scan_phase2<<<nscan / 256, 256>>>(a, bfr, st_i, st_r);
    // 4) z = sr @ mix_w^T + mix_b  -> fp32 z
    gemm_mma<0><<<dim3(OUT_/128, NTOK/128), 256, SMEM_MMA>>>(
        srh, w2h, mix_b, zbuf, KMIX, OUT_);
    // 5) LN + gated mix
    ln_epilogue<<<NTOK, 256>>>(out);
}